// round 17
// baseline (speedup 1.0000x reference)
#include <cuda_runtime.h>
#include <cuda_bf16.h>
#include <float.h>

// Problem constants
#define B_   16
#define C_   256
#define H_   128
#define W_   128
#define HW_  (H_ * W_)           // 16384
#define HW4_ (HW_ / 4)           // 4096 float4 pixel-groups per batch
#define KSZ  7
#define PAD  3

#define NTHR      256            // threads per block (8 warps = 2 independent halves)
#define NB        512            // persistent grid, proven co-resident at 4 CTAs/SM
#define GROUP_B   2              // batches per chunk (32 MiB of x)
#define NCHUNK    (B_ / GROUP_B) // 8
#define TILE_PG   8              // pixel-groups per tile (32 pixels = quarter row)
#define TILES_PER_ROW 4          // 128 px row / 32 px tile
#define NVTILE    (NB * 2)       // 1024 virtual tiles per chunk (one per half)

// Scratch maps (per batch, per pixel)
__device__ float g_max[B_ * HW_];   // 1 MiB
__device__ float g_avg[B_ * HW_];   // 1 MiB

// Per (batch,row) ready counters: row ready when == TILES_PER_ROW
__device__ unsigned g_flag[B_ * H_];

// One-shot start barrier (generation-based: replay-safe)
__device__ unsigned g_bar_cnt = 0;
__device__ volatile unsigned g_bar_gen = 0;

__device__ __forceinline__ void grid_barrier() {
    __syncthreads();
    if (threadIdx.x == 0) {
        unsigned gen = g_bar_gen;
        __threadfence();
        if (atomicAdd(&g_bar_cnt, 1u) == NB - 1u) {
            g_bar_cnt = 0u;
            __threadfence();
            g_bar_gen = gen + 1u;
        } else {
            while (g_bar_gen == gen) { __nanosleep(64); }
            __threadfence();
        }
    }
    __syncthreads();
}

// Named barrier over one 128-thread half (warps 0-3 -> id 1, warps 4-7 -> id 2).
// bar.sync carries CTA-scope memory-ordering semantics like __syncthreads.
__device__ __forceinline__ void half_bar(int half) {
    asm volatile("bar.sync %0, 128;" :: "r"(half + 1) : "memory");
}

// ---------------------------------------------------------------------------
// Persistent kernel. Each 256-thread CTA = two INDEPENDENT 128-thread halves
// (named-barrier synced), giving 8 phase-decorrelated work streams per SM on
// the proven 4-CTA/SM launch geometry. Each half, per iteration k:
//   phase1(chunk k)   reduce its 32-px tile over 256 channels, signal row flag
//   phase2(chunk k-1) flags a full iteration old -> rarely blocks;
//                     7x7 conv + hsigmoid gates, multiply 256 ch (x from L2)
// ---------------------------------------------------------------------------
__global__ void __launch_bounds__(NTHR, 4)
fused_kernel(const float* __restrict__ x,
             const float* __restrict__ conv_w,
             const float* __restrict__ conv_b,
             float* __restrict__ out) {
    __shared__ float4 s_mx[NTHR];                    // per-half slices of 128
    __shared__ float4 s_sm[NTHR];
    __shared__ float  s_w[2 * KSZ * KSZ];
    __shared__ __align__(16) float s_gate[2 * TILE_PG * 4];  // 32 gates per half
    __shared__ float  s_bias;

    if (threadIdx.x < 2 * KSZ * KSZ) s_w[threadIdx.x] = conv_w[threadIdx.x];
    if (threadIdx.x == 0) s_bias = conv_b[0];

    // Zero flags, then one global barrier so nobody signals before zeroing.
    {
        int idx = blockIdx.x * NTHR + threadIdx.x;
        if (idx < B_ * H_) g_flag[idx] = 0u;
    }
    grid_barrier();   // also makes s_w/s_bias visible to all

    const int half = threadIdx.x >> 7;     // 0 or 1 (warp-aligned)
    const int ht   = threadIdx.x & 127;    // thread within half

    const int vt   = blockIdx.x * 2 + half;    // virtual tile 0..1023
    const int b_l  = vt >> 9;                  // local batch within chunk (0/1)
    const int tib  = vt & 511;                 // tile within batch
    const int pg0  = tib * TILE_PG;            // first pixel-group of tile
    const int hrow = tib >> 2;                 // pixel row (4 tiles per row)

    const int px   = ht & 7;               // pixel-group within tile (0..7)
    const int cs   = ht >> 3;              // channel slice (0..15), 16 ch each
    const int sb   = half * 128;           // smem slice base
    const int hlo  = (hrow - PAD < 0) ? 0 : hrow - PAD;
    const int hhi  = (hrow + PAD > H_ - 1) ? H_ - 1 : hrow + PAD;
    const int nrows = hhi - hlo + 1;       // <= 7

    for (int k = 0; k <= NCHUNK; k++) {
        // ================= Phase 1: channel reduction, chunk k =============
        if (k < NCHUNK) {
            const int b  = k * GROUP_B + b_l;
            const int pg = pg0 + px;

            const float4* __restrict__ xb =
                reinterpret_cast<const float4*>(x)
                + ((size_t)(b * C_ + cs * 16)) * HW4_ + pg;

            float4 mx = make_float4(-FLT_MAX, -FLT_MAX, -FLT_MAX, -FLT_MAX);
            float4 sm = make_float4(0.f, 0.f, 0.f, 0.f);

            #pragma unroll
            for (int grp = 0; grp < 2; grp++) {      // 2 x 8 channels (MLP=8)
                float4 v[8];
                #pragma unroll
                for (int u = 0; u < 8; u++)
                    v[u] = xb[(size_t)(grp * 8 + u) * HW4_];
                #pragma unroll
                for (int u = 0; u < 8; u++) {
                    mx.x = fmaxf(mx.x, v[u].x); sm.x += v[u].x;
                    mx.y = fmaxf(mx.y, v[u].y); sm.y += v[u].y;
                    mx.z = fmaxf(mx.z, v[u].z); sm.z += v[u].z;
                    mx.w = fmaxf(mx.w, v[u].w); sm.w += v[u].w;
                }
            }

            s_mx[sb + ht] = mx;
            s_sm[sb + ht] = sm;

            // Tree over 16 channel slices (stride = sh*8 threads, within half)
            #pragma unroll
            for (int sh = 8; sh >= 1; sh >>= 1) {
                half_bar(half);
                if (ht < sh * 8) {
                    float4 omx = s_mx[sb + ht + sh * 8];
                    float4 osm = s_sm[sb + ht + sh * 8];
                    float4 a = s_mx[sb + ht];
                    float4 s = s_sm[sb + ht];
                    a.x = fmaxf(a.x, omx.x); s.x += osm.x;
                    a.y = fmaxf(a.y, omx.y); s.y += osm.y;
                    a.z = fmaxf(a.z, omx.z); s.z += osm.z;
                    a.w = fmaxf(a.w, omx.w); s.w += osm.w;
                    s_mx[sb + ht] = a;
                    s_sm[sb + ht] = s;
                }
            }
            half_bar(half);

            if (ht < TILE_PG) {
                float4 fm = s_mx[sb + ht];
                float4 fs = s_sm[sb + ht];
                const float inv_c = 1.0f / (float)C_;
                fs.x *= inv_c; fs.y *= inv_c; fs.z *= inv_c; fs.w *= inv_c;
                reinterpret_cast<float4*>(g_max)[b * HW4_ + pg0 + ht] = fm;
                reinterpret_cast<float4*>(g_avg)[b * HW4_ + pg0 + ht] = fs;
            }
            half_bar(half);                // map stores ordered before signal
            if (ht == 0) {
                __threadfence();           // release: maps visible before flag
                atomicAdd(&g_flag[b * H_ + hrow], 1u);
            }
        }

        // ============ Phase 2: gates + multiply, chunk k-1 =================
        if (k > 0) {
            const int b = (k - 1) * GROUP_B + b_l;

            // Wait halo rows (signaled a full iteration ago -> rarely blocks)
            if (ht < nrows) {
                unsigned* f = &g_flag[b * H_ + hlo + ht];
                while (atomicAdd(f, 0u) < (unsigned)TILES_PER_ROW) { __nanosleep(32); }
                __threadfence();           // acquire
            }
            half_bar(half);

            // 2a: threads 0..31 of the half compute the tile's 32 gates
            if (ht < TILE_PG * 4) {
                const int p = pg0 * 4 + ht;
                const int h = p >> 7;
                const int w = p & (W_ - 1);
                const float* __restrict__ mp = g_max + b * HW_;
                const float* __restrict__ ap = g_avg + b * HW_;

                float acc = s_bias;
                #pragma unroll
                for (int kh = 0; kh < KSZ; kh++) {
                    int hh = h + kh - PAD;
                    if (hh < 0 || hh >= H_) continue;
                    int rowoff = hh * W_;
                    #pragma unroll
                    for (int kw = 0; kw < KSZ; kw++) {
                        int ww = w + kw - PAD;
                        if (ww < 0 || ww >= W_) continue;
                        int q = rowoff + ww;
                        acc = fmaf(s_w[kh * KSZ + kw],      mp[q], acc);
                        acc = fmaf(s_w[49 + kh * KSZ + kw], ap[q], acc);
                    }
                }
                s_gate[half * 32 + ht] =
                    fminf(fmaxf(acc + 3.0f, 0.0f), 6.0f) * (1.0f / 6.0f);
            }
            half_bar(half);

            // 2b: multiply all 256 channels for this tile (x from L2).
            const int pg = pg0 + px;
            const float4 gv = reinterpret_cast<float4*>(s_gate)[half * 8 + px];

            const float4* __restrict__ xb =
                reinterpret_cast<const float4*>(x) + ((size_t)b * C_) * HW4_ + pg;
            float4* __restrict__ ob =
                reinterpret_cast<float4*>(out) + ((size_t)b * C_) * HW4_ + pg;

            #pragma unroll
            for (int grp = 0; grp < 2; grp++) {      // 2 x 8 channels (MLP=8)
                float4 v[8];
                int cbase = cs + grp * 128;          // c = cs + u*16 (+128)
                #pragma unroll
                for (int u = 0; u < 8; u++)
                    v[u] = __ldcs(xb + (size_t)(cbase + u * 16) * HW4_);
                #pragma unroll
                for (int u = 0; u < 8; u++) {
                    float4 ov;
                    ov.x = v[u].x * gv.x;
                    ov.y = v[u].y * gv.y;
                    ov.z = v[u].z * gv.z;
                    ov.w = v[u].w * gv.w;
                    __stcs(ob + (size_t)(cbase + u * 16) * HW4_, ov);
                }
            }
            half_bar(half);    // s_gate / s_mx reuse safety for next iteration
        }
    }
}

// ---------------------------------------------------------------------------
extern "C" void kernel_launch(void* const* d_in, const int* in_sizes, int n_in,
                              void* d_out, int out_size) {
    const float* x      = (const float*)d_in[0];  // [16,256,128,128]
    const float* conv_w = (const float*)d_in[1];  // [1,2,7,7] = 98 floats
    const float* conv_b = (const float*)d_in[2];  // [1]
    float* out = (float*)d_out;

    fused_kernel<<<NB, NTHR>>>(x, conv_w, conv_b, out);
}